// round 9
// baseline (speedup 1.0000x reference)
#include <cuda_runtime.h>
#include <cuda_bf16.h>
#include <math.h>
#include <stdint.h>

// ---------------------------------------------------------------------------
// Transformer forward, 4 layers. B=4, L=1024, E=1024, H=16, d=64, MLP=4096.
// GEMMs: packed fp32x2 (FFMA2) SGEMM — full fp32 precision, one pass.
// Rationale: legacy HMMA on sm_103 base target caps at ~62 TF/s regardless of
// kernel quality (measured R4 vs R8); FFMA2 peak ~70 TF/s in ONE pass vs 3.
// ---------------------------------------------------------------------------

#define NUM_LAYERS 4
#define EMBED 1024
#define HEADS 16
#define HEAD_DIM 64
#define MLPDIM 4096
#define BATCH 4
#define SEQ 1024
#define MTOT (BATCH * SEQ)
#define EPS_LN 1e-6f

#define NSLAB ((size_t)MTOT * EMBED)            // 4 M floats

// fp32 scratch: x,q,k,v,u,a,h,z (8 slabs) + m (16 M)
__device__ float g_f[8 * NSLAB + (size_t)MTOT * MLPDIM];

// -------------------- PTX helpers ------------------------------------------
__device__ __forceinline__ uint32_t s2u(const void* p) {
    uint32_t a;
    asm("{ .reg .u64 t; cvta.to.shared.u64 t, %1; cvt.u32.u64 %0, t; }"
        : "=r"(a) : "l"(p));
    return a;
}
__device__ __forceinline__ void cp16(uint32_t sdst, const void* gsrc) {
    asm volatile("cp.async.cg.shared.global [%0], [%1], 16;"
                 :: "r"(sdst), "l"(gsrc) : "memory");
}
#define CP_COMMIT() asm volatile("cp.async.commit_group;" ::: "memory")
#define CP_WAIT(n)  asm volatile("cp.async.wait_group %0;" :: "n"(n) : "memory")

__device__ __forceinline__ void fma2(unsigned long long& acc,
                                     unsigned long long a2,
                                     unsigned long long b2) {
    asm("fma.rn.f32x2 %0, %1, %2, %0;" : "+l"(acc) : "l"(a2), "l"(b2));
}
__device__ __forceinline__ unsigned long long splat2(float a) {
    unsigned long long r;
    asm("mov.b64 %0, {%1, %1};" : "=l"(r) : "f"(a));
    return r;
}
__device__ __forceinline__ float2 unpack2(unsigned long long p) {
    float2 r;
    asm("mov.b64 {%0, %1}, %2;" : "=f"(r.x), "=f"(r.y) : "l"(p));
    return r;
}

// -------------------- fp32x2 SGEMM -----------------------------------------
// C[M][N] = alpha*(A@B + bias), A [M,K] fp32 rm, B [K,N] fp32 rm (weights
// used in native layout — no prep). Tile 128x128, BK=16, 256 thr, 8x8/thread.
#define FBM 128
#define FBN 128
#define FBK 16
#define FNSTAGE 4
#define BS_STRIDE 132                              // floats (528 B, 16B mult)
#define ARAW_B (FBM * FBK * 4)                     // 8192 B
#define BS_B (FBK * BS_STRIDE * 4)                 // 8448 B
#define FSTAGE_B (ARAW_B + BS_B)                   // 16640 B
#define AST_B (FBK * BS_STRIDE * 4)                // 8448 B transposed A
#define FGEMM_SMEM (FNSTAGE * FSTAGE_B + AST_B)    // 75008 B

__global__ __launch_bounds__(256, 2) void sgemm_f2(
    const float* __restrict__ A, const float* __restrict__ B,
    const float* __restrict__ bias, float* __restrict__ C,
    int N, int K, float alpha, int relu)
{
    extern __shared__ __align__(16) char fsm[];
    const uint32_t sbase = s2u(fsm);
    const uint32_t ast = sbase + FNSTAGE * FSTAGE_B;    // As_t[k][m]

    const int tid = threadIdx.x;
    const int tx = tid & 15;            // n: 8 cols at tx*8
    const int ty = tid >> 4;            // m: 8 rows at ty*8
    const int m0 = blockIdx.y * FBM;
    const int n0 = blockIdx.x * FBN;

    const float* pA = A + (size_t)m0 * K;
    const float* pB = B + n0;

    // load indices (2 x cp16 each for A and B)
    const int a_row0 = tid >> 2;                 // 0..63  (+64 for i=1)
    const int a_col4 = (tid & 3) * 4;            // k offset in floats
    const int b_k0 = tid >> 5;                   // 0..7   (+8 for i=1)
    const int b_n16 = (tid & 31) * 4;            // n offset in floats

    unsigned long long acc[8][4];
    #pragma unroll
    for (int i = 0; i < 8; i++)
        #pragma unroll
        for (int j = 0; j < 4; j++) acc[i][j] = 0ull;

    const int NC = K / FBK;

    auto load_stage = [&](int s, int c) {
        const uint32_t st = sbase + s * FSTAGE_B;
        const int k0 = c * FBK;
        #pragma unroll
        for (int i = 0; i < 2; i++) {
            int row = a_row0 + i * 64;
            cp16(st + (uint32_t)((row * FBK + a_col4) * 4),
                 pA + (size_t)row * K + k0 + a_col4);
        }
        #pragma unroll
        for (int i = 0; i < 2; i++) {
            int kk = b_k0 + i * 8;
            cp16(st + ARAW_B + (uint32_t)((kk * BS_STRIDE + b_n16) * 4),
                 pB + (size_t)(k0 + kk) * N + b_n16);
        }
        CP_COMMIT();
    };

    load_stage(0, 0);
    load_stage(1, 1);
    load_stage(2, 2);

    for (int c = 0; c < NC; c++) {
        CP_WAIT(2);
        __syncthreads();

        const uint32_t st = sbase + (c % FNSTAGE) * FSTAGE_B;

        // transpose Araw[m][k] -> As_t[k][m]
        #pragma unroll
        for (int i = 0; i < 2; i++) {
            int idx = tid + i * 256;
            int row = idx >> 2;
            int c4 = (idx & 3) * 4;
            float4 v = *(const float4*)(fsm + (st - sbase) + (row * FBK + c4) * 4);
            float* dst = (float*)(fsm + (ast - sbase));
            dst[(c4 + 0) * BS_STRIDE + row] = v.x;
            dst[(c4 + 1) * BS_STRIDE + row] = v.y;
            dst[(c4 + 2) * BS_STRIDE + row] = v.z;
            dst[(c4 + 3) * BS_STRIDE + row] = v.w;
        }
        __syncthreads();

        // issue next loads (stage slot (c+3)%4 is free; Bs[c] read below is
        // in a different slot since FNSTAGE=4 > 3 in flight)
        if (c + 3 < NC) load_stage((c + 3) % FNSTAGE, c + 3);

        const float* At = (const float*)(fsm + (ast - sbase));
        const char* Bst = fsm + (st - sbase) + ARAW_B;
        #pragma unroll
        for (int kk = 0; kk < FBK; kk++) {
            float4 a4a = *(const float4*)(At + kk * BS_STRIDE + ty * 8);
            float4 a4b = *(const float4*)(At + kk * BS_STRIDE + ty * 8 + 4);
            ulonglong2 bpa = *(const ulonglong2*)(Bst + (kk * BS_STRIDE + tx * 8) * 4);
            ulonglong2 bpb = *(const ulonglong2*)(Bst + (kk * BS_STRIDE + tx * 8 + 4) * 4);
            unsigned long long b2[4] = {bpa.x, bpa.y, bpb.x, bpb.y};
            float av[8] = {a4a.x, a4a.y, a4a.z, a4a.w,
                           a4b.x, a4b.y, a4b.z, a4b.w};
            #pragma unroll
            for (int i = 0; i < 8; i++) {
                unsigned long long a2 = splat2(av[i]);
                fma2(acc[i][0], a2, b2[0]);
                fma2(acc[i][1], a2, b2[1]);
                fma2(acc[i][2], a2, b2[2]);
                fma2(acc[i][3], a2, b2[3]);
            }
        }
        __syncthreads();
    }

    // epilogue
    float bb[8];
    #pragma unroll
    for (int j = 0; j < 8; j++) bb[j] = bias[n0 + tx * 8 + j];

    #pragma unroll
    for (int i = 0; i < 8; i++) {
        float* Crow = C + (size_t)(m0 + ty * 8 + i) * N + n0 + tx * 8;
        float4 o0, o1;
        float2 p0 = unpack2(acc[i][0]);
        float2 p1 = unpack2(acc[i][1]);
        float2 p2 = unpack2(acc[i][2]);
        float2 p3 = unpack2(acc[i][3]);
        o0.x = alpha * (p0.x + bb[0]); o0.y = alpha * (p0.y + bb[1]);
        o0.z = alpha * (p1.x + bb[2]); o0.w = alpha * (p1.y + bb[3]);
        o1.x = alpha * (p2.x + bb[4]); o1.y = alpha * (p2.y + bb[5]);
        o1.z = alpha * (p3.x + bb[6]); o1.w = alpha * (p3.y + bb[7]);
        if (relu) {
            o0.x = fmaxf(o0.x, 0.f); o0.y = fmaxf(o0.y, 0.f);
            o0.z = fmaxf(o0.z, 0.f); o0.w = fmaxf(o0.w, 0.f);
            o1.x = fmaxf(o1.x, 0.f); o1.y = fmaxf(o1.y, 0.f);
            o1.z = fmaxf(o1.z, 0.f); o1.w = fmaxf(o1.w, 0.f);
        }
        *(float4*)Crow = o0;
        *(float4*)(Crow + 4) = o1;
    }
}

// -------------------- block reductions (256 threads) -----------------------
__device__ __forceinline__ float block_sum256(float v, float* red) {
    #pragma unroll
    for (int o = 16; o; o >>= 1) v += __shfl_xor_sync(0xffffffffu, v, o);
    int t = threadIdx.x;
    if ((t & 31) == 0) red[t >> 5] = v;
    __syncthreads();
    float r = (t < 8) ? red[t] : 0.f;
    if (t < 32) {
        #pragma unroll
        for (int o = 4; o; o >>= 1) r += __shfl_xor_sync(0xffffffffu, r, o);
        if (t == 0) red[0] = r;
    }
    __syncthreads();
    r = red[0];
    __syncthreads();
    return r;
}

__device__ __forceinline__ float block_max256(float v, float* red) {
    #pragma unroll
    for (int o = 16; o; o >>= 1) v = fmaxf(v, __shfl_xor_sync(0xffffffffu, v, o));
    int t = threadIdx.x;
    if ((t & 31) == 0) red[t >> 5] = v;
    __syncthreads();
    float r = (t < 8) ? red[t] : -3.4e38f;
    if (t < 32) {
        #pragma unroll
        for (int o = 4; o; o >>= 1) r = fmaxf(r, __shfl_xor_sync(0xffffffffu, r, o));
        if (t == 0) red[0] = r;
    }
    __syncthreads();
    r = red[0];
    __syncthreads();
    return r;
}

// -------------------- fused attention: one block per (q row, b, h) ---------
__global__ __launch_bounds__(256) void attn_fused(
    const float* __restrict__ gq, const float* __restrict__ gk,
    const float* __restrict__ gv, float* __restrict__ gu)
{
    __shared__ float qrow[HEAD_DIM];
    __shared__ float P[SEQ];
    __shared__ float red[32];
    __shared__ float Uacc[4][HEAD_DIM];

    const int q  = blockIdx.x;
    const int bh = blockIdx.y;
    const int b  = bh >> 4;
    const int h  = bh & 15;
    const int t  = threadIdx.x;

    const float* qb = gq + ((size_t)b * SEQ + q) * EMBED + h * HEAD_DIM;
    const float* kb = gk + (size_t)b * SEQ * EMBED + h * HEAD_DIM;
    const float* vb = gv + (size_t)b * SEQ * EMBED + h * HEAD_DIM;

    if (t < 16) ((float4*)qrow)[t] = ((const float4*)qb)[t];
    __syncthreads();

    float s[4];
    #pragma unroll
    for (int j = 0; j < 4; j++) {
        const float* krow = kb + (size_t)(t + j * 256) * EMBED;
        float acc = 0.f;
        #pragma unroll
        for (int d4 = 0; d4 < 16; d4++) {
            float4 kv = ((const float4*)krow)[d4];
            acc = fmaf(qrow[d4 * 4 + 0], kv.x, acc);
            acc = fmaf(qrow[d4 * 4 + 1], kv.y, acc);
            acc = fmaf(qrow[d4 * 4 + 2], kv.z, acc);
            acc = fmaf(qrow[d4 * 4 + 3], kv.w, acc);
        }
        s[j] = acc;
    }

    float mx = fmaxf(fmaxf(s[0], s[1]), fmaxf(s[2], s[3]));
    mx = block_max256(mx, red);
    float sum = 0.f;
    #pragma unroll
    for (int j = 0; j < 4; j++) { s[j] = __expf(s[j] - mx); sum += s[j]; }
    sum = block_sum256(sum, red);
    float inv = 1.f / sum;
    #pragma unroll
    for (int j = 0; j < 4; j++) P[t + j * 256] = s[j] * inv;
    __syncthreads();

    const int d = t & 63;
    const int slice = t >> 6;
    float u = 0.f;
    const int kbeg = slice * 256;
    #pragma unroll 4
    for (int k = kbeg; k < kbeg + 256; k++)
        u = fmaf(P[k], vb[(size_t)k * EMBED + d], u);
    Uacc[slice][d] = u;
    __syncthreads();

    if (t < HEAD_DIM) {
        float r2 = Uacc[0][t] + Uacc[1][t] + Uacc[2][t] + Uacc[3][t];
        gu[((size_t)b * SEQ + q) * EMBED + h * HEAD_DIM + t] = r2;
    }
}

// -------------------- residual + layernorm ---------------------------------
__global__ __launch_bounds__(256) void ln_residual(
    const float* __restrict__ a, const float* __restrict__ res,
    const float* __restrict__ sc, const float* __restrict__ bi,
    float* __restrict__ out)
{
    __shared__ float red[32];
    const size_t row = blockIdx.x;
    const int t = threadIdx.x;
    float4 a4 = ((const float4*)(a + row * EMBED))[t];
    float4 r4 = ((const float4*)(res + row * EMBED))[t];
    float4 v;
    v.x = a4.x + r4.x; v.y = a4.y + r4.y; v.z = a4.z + r4.z; v.w = a4.w + r4.w;
    float s = v.x + v.y + v.z + v.w;
    s = block_sum256(s, red);
    float mean = s * (1.f / EMBED);
    v.x -= mean; v.y -= mean; v.z -= mean; v.w -= mean;
    float sq = v.x * v.x + v.y * v.y + v.z * v.z + v.w * v.w;
    sq = block_sum256(sq, red);
    float inv = rsqrtf(sq * (1.f / EMBED) + EPS_LN);
    float4 s4 = ((const float4*)sc)[t];
    float4 b4 = ((const float4*)bi)[t];
    float4 o;
    o.x = v.x * inv * s4.x + b4.x;
    o.y = v.y * inv * s4.y + b4.y;
    o.z = v.z * inv * s4.z + b4.z;
    o.w = v.w * inv * s4.w + b4.w;
    ((float4*)(out + row * EMBED))[t] = o;
}

// -------------------- copy-in ----------------------------------------------
__global__ __launch_bounds__(256) void copy_in_k(
    const float* __restrict__ src, float* __restrict__ dst)
{
    size_t i = (size_t)blockIdx.x * 256 + threadIdx.x;
    ((float4*)dst)[i] = ((const float4*)src)[i];
}

// -------------------- input identification ---------------------------------
struct Inputs {
    const float *queries, *Wq, *bq, *Wk, *bk, *Wv, *bv, *Wo, *bo;
    const float *l1s, *l1b, *l2s, *l2b, *W1, *b1, *W2, *b2;
};

static void map_inputs(void* const* d_in, const int* in_sizes, Inputs* I)
{
    const int SZ_Q = MTOT * EMBED;
    const int SZ_W = NUM_LAYERS * EMBED * MLPDIM;
    const int SZ_B1 = NUM_LAYERS * MLPDIM;
    const int SZ_V = NUM_LAYERS * EMBED;

    static const int dict_pat[17] = {SZ_Q,SZ_Q,SZ_V,SZ_Q,SZ_V,SZ_Q,SZ_V,SZ_Q,
                                     SZ_V,SZ_V,SZ_V,SZ_V,SZ_V,SZ_W,SZ_B1,SZ_W,SZ_V};
    static const int alpha_pat[17] = {SZ_W,SZ_W,SZ_Q,SZ_Q,SZ_Q,SZ_Q,SZ_B1,SZ_V,
                                      SZ_V,SZ_V,SZ_V,SZ_V,SZ_V,SZ_V,SZ_V,SZ_V,SZ_Q};
    bool is_dict = true, is_alpha = true;
    for (int i = 0; i < 17; i++) {
        if (in_sizes[i] != dict_pat[i])  is_dict = false;
        if (in_sizes[i] != alpha_pat[i]) is_alpha = false;
    }
    const float** p = (const float**)d_in;
    if (is_alpha) {
        I->W1 = p[0];  I->W2 = p[1];  I->Wk = p[2];  I->Wo = p[3];
        I->Wq = p[4];  I->Wv = p[5];  I->b1 = p[6];  I->b2 = p[7];
        I->bk = p[8];  I->bo = p[9];  I->bq = p[10]; I->bv = p[11];
        I->l1b = p[12];I->l1s = p[13];I->l2b = p[14];I->l2s = p[15];
        I->queries = p[16];
    } else if (is_dict) {
        I->queries = p[0];  I->Wq = p[1];  I->bq = p[2];  I->Wk = p[3];
        I->bk = p[4];       I->Wv = p[5];  I->bv = p[6];  I->Wo = p[7];
        I->bo = p[8];       I->l1s = p[9]; I->l1b = p[10];I->l2s = p[11];
        I->l2b = p[12];     I->W1 = p[13]; I->b1 = p[14]; I->W2 = p[15];
        I->b2 = p[16];
    } else {
        const float* cq[8]; int nq = 0;
        const float* cw[4]; int nw = 0;
        const float* cv[12]; int nv = 0;
        const float* cb1 = 0;
        for (int i = 0; i < 17; i++) {
            if (in_sizes[i] == SZ_Q && nq < 8) cq[nq++] = p[i];
            else if (in_sizes[i] == SZ_W && nw < 4) cw[nw++] = p[i];
            else if (in_sizes[i] == SZ_B1) cb1 = p[i];
            else if (nv < 12) cv[nv++] = p[i];
        }
        I->queries = cq[0]; I->Wq = cq[1]; I->Wk = cq[2]; I->Wv = cq[3]; I->Wo = cq[4];
        I->W1 = cw[0]; I->W2 = cw[1]; I->b1 = cb1;
        I->bq = cv[0]; I->bk = cv[1]; I->bv = cv[2]; I->bo = cv[3];
        I->l1s = cv[4]; I->l1b = cv[5]; I->l2s = cv[6]; I->l2b = cv[7]; I->b2 = cv[8];
    }
}

// -------------------- host orchestration -----------------------------------
static float* sym_addr_f(const void* sym) {
    void* pv = 0;
    cudaGetSymbolAddress(&pv, sym);
    return (float*)pv;
}

extern "C" void kernel_launch(void* const* d_in, const int* in_sizes, int n_in,
                              void* d_out, int out_size)
{
    Inputs I;
    map_inputs(d_in, in_sizes, &I);
    float* out = (float*)d_out;

    cudaFuncSetAttribute(sgemm_f2, cudaFuncAttributeMaxDynamicSharedMemorySize,
                         FGEMM_SMEM);

    float* fbase = sym_addr_f(g_f);
    float* x = fbase + 0 * NSLAB;
    float* q = fbase + 1 * NSLAB;
    float* k = fbase + 2 * NSLAB;
    float* v = fbase + 3 * NSLAB;
    float* u = fbase + 4 * NSLAB;
    float* a = fbase + 5 * NSLAB;
    float* h = fbase + 6 * NSLAB;
    float* z = fbase + 7 * NSLAB;
    float* m = fbase + 8 * NSLAB;

    const float qscale = 1.f / sqrtf((float)HEAD_DIM);
    const int CP_E = (int)(NSLAB / 1024);

    auto GEMM = [&](const float* Ap, const float* Bp, const float* bias,
                    float* Cp, int N, int K, float alpha, int relu) {
        sgemm_f2<<<dim3(N / FBN, MTOT / FBM), 256, FGEMM_SMEM>>>(
            Ap, Bp, bias, Cp, N, K, alpha, relu);
    };

    copy_in_k<<<CP_E, 256>>>(I.queries, x);

    for (int l = 0; l < NUM_LAYERS; l++) {
        const float* Wq_l = I.Wq + (size_t)l * EMBED * EMBED;
        const float* Wk_l = I.Wk + (size_t)l * EMBED * EMBED;
        const float* Wv_l = I.Wv + (size_t)l * EMBED * EMBED;
        const float* Wo_l = I.Wo + (size_t)l * EMBED * EMBED;
        const float* W1_l = I.W1 + (size_t)l * EMBED * MLPDIM;
        const float* W2_l = I.W2 + (size_t)l * MLPDIM * EMBED;
        const float* bq_l = I.bq + (size_t)l * EMBED;
        const float* bk_l = I.bk + (size_t)l * EMBED;
        const float* bv_l = I.bv + (size_t)l * EMBED;
        const float* bo_l = I.bo + (size_t)l * EMBED;
        const float* b1_l = I.b1 + (size_t)l * MLPDIM;
        const float* b2_l = I.b2 + (size_t)l * EMBED;
        const float* l1s = I.l1s + (size_t)l * EMBED;
        const float* l1b = I.l1b + (size_t)l * EMBED;
        const float* l2s = I.l2s + (size_t)l * EMBED;
        const float* l2b = I.l2b + (size_t)l * EMBED;

        GEMM(x, Wq_l, bq_l, q, EMBED, EMBED, qscale, 0);
        GEMM(x, Wk_l, bk_l, k, EMBED, EMBED, 1.f, 0);
        GEMM(x, Wv_l, bv_l, v, EMBED, EMBED, 1.f, 0);

        attn_fused<<<dim3(SEQ, BATCH * HEADS), 256>>>(q, k, v, u);

        GEMM(u, Wo_l, bo_l, a, EMBED, EMBED, 1.f, 0);
        ln_residual<<<MTOT, 256>>>(a, x, l1s, l1b, h);

        GEMM(h, W1_l, b1_l, m, MLPDIM, EMBED, 1.f, 1);
        GEMM(m, W2_l, b2_l, z, EMBED, MLPDIM, 1.f, 0);
        ln_residual<<<MTOT, 256>>>(z, h, l2s, l2b, x);
    }

    cudaMemcpyAsync(out, x, NSLAB * sizeof(float), cudaMemcpyDeviceToDevice, 0);
}